// round 5
// baseline (speedup 1.0000x reference)
#include <cuda_runtime.h>
#include <math.h>
#include <stdint.h>

// Problem constants
#define NB 256        // batch B
#define NN 1024       // N
#define NK 64         // K
#define INV_TEMP 5.0f // 1/0.2
#define LN_EPS 1e-5f

// Scratch (static device globals; allocation inside kernel_launch is forbidden)
static __device__ float g_S[NN * NN];                    // sinkhorn(A_logits)   4 MB
static __device__ float g_W[NN * NK * NK];               // per-block sinkhorn  16 MB
static __device__ float g_XL[(size_t)NB * NN * NK];      // x_local [b][n][k]   64 MB
static __device__ float g_YT[(size_t)NB * NK * NN];      // normalized [b*K+k][n] 64 MB

// ---------------------------------------------------------------------------
// Kernel 1: row pass of log_sinkhorn on A_logits.
// la = logits/T ; la -= logsumexp(la, axis=-1) ; store to g_S.
// One block per row, 256 threads, 4 elements/thread.
// ---------------------------------------------------------------------------
__global__ void k_sink_row(const float* __restrict__ logits) {
    const int row = blockIdx.x;
    const int t = threadIdx.x;
    const float* rp = logits + (size_t)row * NN;
    float v[4];
    float m = -1e30f;
#pragma unroll
    for (int q = 0; q < 4; ++q) {
        v[q] = rp[t + 256 * q] * INV_TEMP;
        m = fmaxf(m, v[q]);
    }
    __shared__ float red[256];
    red[t] = m;
    __syncthreads();
    for (int s = 128; s > 0; s >>= 1) {
        if (t < s) red[t] = fmaxf(red[t], red[t + s]);
        __syncthreads();
    }
    m = red[0];
    __syncthreads();
    float acc = 0.f;
#pragma unroll
    for (int q = 0; q < 4; ++q) acc += expf(v[q] - m);
    red[t] = acc;
    __syncthreads();
    for (int s = 128; s > 0; s >>= 1) {
        if (t < s) red[t] += red[t + s];
        __syncthreads();
    }
    const float lse = logf(red[0]) + m;
    float* op = g_S + (size_t)row * NN;
#pragma unroll
    for (int q = 0; q < 4; ++q) op[t + 256 * q] = v[q] - lse;
}

// ---------------------------------------------------------------------------
// Kernel 2: column pass + exp. Each block owns 32 columns; 8-way row
// parallelism per column with online logsumexp, then in-place exp.
// ---------------------------------------------------------------------------
__global__ void k_sink_col() {
    const int c0 = blockIdx.x * 32;
    const int t = threadIdx.x;
    const int c = t & 31;
    const int ry = t >> 5;  // 0..7
    float m = -1e30f, s = 0.f;
    for (int i = ry; i < NN; i += 8) {
        float v = g_S[(size_t)i * NN + c0 + c];
        float mn = fmaxf(m, v);
        s = s * expf(m - mn) + expf(v - mn);
        m = mn;
    }
    __shared__ float sm[8][32];
    __shared__ float ss[8][32];
    __shared__ float cl[32];
    sm[ry][c] = m;
    ss[ry][c] = s;
    __syncthreads();
    if (t < 32) {
        float M = -1e30f;
#pragma unroll
        for (int q = 0; q < 8; ++q) M = fmaxf(M, sm[q][t]);
        float S = 0.f;
#pragma unroll
        for (int q = 0; q < 8; ++q) S += ss[q][t] * expf(sm[q][t] - M);
        cl[t] = logf(S) + M;
    }
    __syncthreads();
    const float myl = cl[c];
    for (int i = ry; i < NN; i += 8) {
        size_t idx = (size_t)i * NN + c0 + c;
        g_S[idx] = expf(g_S[idx] - myl);
    }
}

// ---------------------------------------------------------------------------
// Kernel 3: W[t] = log_sinkhorn( (W1[t,:] . W_V) / T ) for each t.
// One block per t; 64x64 logits live in smem; row LSE then column LSE.
// ---------------------------------------------------------------------------
__global__ void k_wsink(const float* __restrict__ W1, const float* __restrict__ WV) {
    const int n = blockIdx.x;
    const int t = threadIdx.x;
    __shared__ float L[64][65];
    __shared__ float w1[8];
    __shared__ float rl[64];
    __shared__ float cl[64];
    if (t < 8) w1[t] = W1[n * 8 + t];
    __syncthreads();
#pragma unroll
    for (int q = 0; q < 16; ++q) {
        int idx = t + 256 * q;
        float acc = 0.f;
#pragma unroll
        for (int k = 0; k < 8; ++k) acc += w1[k] * WV[k * 4096 + idx];
        L[idx >> 6][idx & 63] = acc * INV_TEMP;
    }
    __syncthreads();
    if (t < 64) {  // row logsumexp (over last axis e)
        float m = -1e30f;
        for (int e = 0; e < 64; ++e) m = fmaxf(m, L[t][e]);
        float s = 0.f;
        for (int e = 0; e < 64; ++e) s += expf(L[t][e] - m);
        rl[t] = logf(s) + m;
    }
    __syncthreads();
#pragma unroll
    for (int q = 0; q < 16; ++q) {
        int idx = t + 256 * q;
        L[idx >> 6][idx & 63] -= rl[idx >> 6];
    }
    __syncthreads();
    if (t < 64) {  // column logsumexp (over axis d)
        float m = -1e30f;
        for (int d = 0; d < 64; ++d) m = fmaxf(m, L[d][t]);
        float s = 0.f;
        for (int d = 0; d < 64; ++d) s += expf(L[d][t] - m);
        cl[t] = logf(s) + m;
    }
    __syncthreads();
    float* wp = g_W + (size_t)n * 4096;
#pragma unroll
    for (int q = 0; q < 16; ++q) {
        int idx = t + 256 * q;
        wp[idx] = expf(L[idx >> 6][idx & 63] - cl[idx & 63]);
    }
}

// ---------------------------------------------------------------------------
// Kernel 4: x_local[b,n,o] = sum_i x[b,n,i] * W[n,i,o].
// Block: one n, 64 batch rows. 16x16 threads, 4x4 microtile. Output stored
// [b][n][k] (coalesced float4 writes).
// ---------------------------------------------------------------------------
__global__ void k_xlocal(const float* __restrict__ x) {
    const int n = blockIdx.x;
    const int b0 = blockIdx.y * 64;
    const int t = threadIdx.x;
    __shared__ float Xs[64][68];
    __shared__ float Ws[64][68];
#pragma unroll
    for (int q = 0; q < 4; ++q) {
        int f4 = t + 256 * q;      // 0..1023
        int row = f4 >> 4;
        int ch = (f4 & 15) << 2;
        float4 vx = *(const float4*)(x + (size_t)(b0 + row) * (NN * NK) + n * NK + ch);
        *(float4*)&Xs[row][ch] = vx;
        float4 vw = *(const float4*)(g_W + (size_t)n * (NK * NK) + row * NK + ch);
        *(float4*)&Ws[row][ch] = vw;
    }
    __syncthreads();
    const int tx = (t & 15) << 2;  // output col o
    const int ty = (t >> 4) << 2;  // output row bb
    float acc[4][4] = {};
#pragma unroll 8
    for (int i = 0; i < 64; ++i) {
        float a[4];
#pragma unroll
        for (int j = 0; j < 4; ++j) a[j] = Xs[ty + j][i];
        float4 bv = *(float4*)&Ws[i][tx];
        float bb[4] = {bv.x, bv.y, bv.z, bv.w};
#pragma unroll
        for (int j = 0; j < 4; ++j)
#pragma unroll
            for (int jj = 0; jj < 4; ++jj)
                acc[j][jj] = fmaf(a[j], bb[jj], acc[j][jj]);
    }
#pragma unroll
    for (int j = 0; j < 4; ++j) {
        float4 o = make_float4(acc[j][0], acc[j][1], acc[j][2], acc[j][3]);
        *(float4*)(g_XL + ((size_t)(b0 + ty + j) * NN + n) * NK + tx) = o;
    }
}

// ---------------------------------------------------------------------------
// Kernel 5: layernorm over n (per (b,k)) + transpose to g_YT[(b*K+k)][n].
// Block: one b, 32 k-columns. Pass 1: coalesced stats. Pass 2: 32x32 smem
// tile transpose so writes are n-contiguous.
// ---------------------------------------------------------------------------
__global__ void k_lnt(const float* __restrict__ gamma2, const float* __restrict__ beta2) {
    const int b = blockIdx.x;
    const int k0 = blockIdx.y * 32;
    const int t = threadIdx.x;
    const int kc = t & 31;
    const int nr = t >> 5;  // 0..7
    const float* base = g_XL + (size_t)b * NN * NK;
    float s = 0.f, s2 = 0.f;
    for (int n = nr; n < NN; n += 8) {
        float v = base[(size_t)n * NK + k0 + kc];
        s += v;
        s2 += v * v;
    }
    __shared__ float ps[8][32];
    __shared__ float ps2[8][32];
    ps[nr][kc] = s;
    ps2[nr][kc] = s2;
    __syncthreads();
    __shared__ float mu[32];
    __shared__ float rstd_s[32];
    if (t < 32) {
        float S = 0.f, S2 = 0.f;
#pragma unroll
        for (int q = 0; q < 8; ++q) { S += ps[q][t]; S2 += ps2[q][t]; }
        float m = S * (1.0f / NN);
        float var = S2 * (1.0f / NN) - m * m;
        mu[t] = m;
        rstd_s[t] = rsqrtf(var + LN_EPS);
    }
    __syncthreads();
    __shared__ float T[32][33];
    for (int nt = 0; nt < NN; nt += 32) {
#pragma unroll
        for (int p = 0; p < 4; ++p) {
            int nl = nr + 8 * p;
            T[nl][kc] = base[(size_t)(nt + nl) * NK + k0 + kc];
        }
        __syncthreads();
#pragma unroll
        for (int p = 0; p < 4; ++p) {
            int kl = nr + 8 * p;
            int n = nt + kc;
            float v = (T[kc][kl] - mu[kl]) * rstd_s[kl];
            v = v * gamma2[n] + beta2[n];
            g_YT[(size_t)(b * NK + k0 + kl) * NN + n] = v;
        }
        __syncthreads();
    }
}

// ---------------------------------------------------------------------------
// Kernel 6: big GEMM, transposed formulation.
//   C[nIdx][r] = sum_m g_S[m][nIdx] * g_YT[r][m],  r = b*64 + k
//   out[b*65536 + nIdx*64 + k] = C[nIdx][r]
// 128x128x16 tile, 256 threads, 8x8 microtile, double-buffered smem.
// All LDG/STG are coalesced float4.
// ---------------------------------------------------------------------------
__global__ void __launch_bounds__(256) k_gemm(float* __restrict__ out) {
    const int br = blockIdx.x;  // r tile (0..127)
    const int bn = blockIdx.y;  // n tile (0..7)
    const int t = threadIdx.x;
    __shared__ float As[2][16][128];
    __shared__ float Bs[2][16][132];
    const int n0 = bn * 128;
    const int r0 = br * 128;

    const int am = t >> 5;            // As rows am, am+8
    const int an = (t & 31) << 2;     // As col chunk
    const int brw = t >> 2;           // Bs source rows brw, brw+64
    const int bq = (t & 3) << 2;      // m chunk within a Y row

    float4 la0, la1, lb0, lb1;
    la0 = *(const float4*)(g_S + (size_t)am * NN + n0 + an);
    la1 = *(const float4*)(g_S + (size_t)(am + 8) * NN + n0 + an);
    lb0 = *(const float4*)(g_YT + (size_t)(r0 + brw) * NN + bq);
    lb1 = *(const float4*)(g_YT + (size_t)(r0 + brw + 64) * NN + bq);
    *(float4*)&As[0][am][an] = la0;
    *(float4*)&As[0][am + 8][an] = la1;
    Bs[0][bq + 0][brw] = lb0.x; Bs[0][bq + 1][brw] = lb0.y;
    Bs[0][bq + 2][brw] = lb0.z; Bs[0][bq + 3][brw] = lb0.w;
    Bs[0][bq + 0][brw + 64] = lb1.x; Bs[0][bq + 1][brw + 64] = lb1.y;
    Bs[0][bq + 2][brw + 64] = lb1.z; Bs[0][bq + 3][brw + 64] = lb1.w;
    __syncthreads();

    const int tx = (t & 15) << 2;  // r micro base
    const int ty = (t >> 4) << 2;  // n micro base
    float acc[8][8] = {};
    int cur = 0;
#pragma unroll 1
    for (int it = 0; it < 64; ++it) {
        if (it < 63) {
            const int m0 = (it + 1) * 16;
            la0 = *(const float4*)(g_S + (size_t)(m0 + am) * NN + n0 + an);
            la1 = *(const float4*)(g_S + (size_t)(m0 + am + 8) * NN + n0 + an);
            lb0 = *(const float4*)(g_YT + (size_t)(r0 + brw) * NN + m0 + bq);
            lb1 = *(const float4*)(g_YT + (size_t)(r0 + brw + 64) * NN + m0 + bq);
        }
#pragma unroll
        for (int kk = 0; kk < 16; ++kk) {
            float ar[8], bv[8];
            *(float4*)(ar)     = *(float4*)&As[cur][kk][ty];
            *(float4*)(ar + 4) = *(float4*)&As[cur][kk][ty + 64];
            *(float4*)(bv)     = *(float4*)&Bs[cur][kk][tx];
            *(float4*)(bv + 4) = *(float4*)&Bs[cur][kk][tx + 64];
#pragma unroll
            for (int i = 0; i < 8; ++i)
#pragma unroll
                for (int j = 0; j < 8; ++j)
                    acc[i][j] = fmaf(ar[i], bv[j], acc[i][j]);
        }
        if (it < 63) {
            const int nxt = cur ^ 1;
            *(float4*)&As[nxt][am][an] = la0;
            *(float4*)&As[nxt][am + 8][an] = la1;
            Bs[nxt][bq + 0][brw] = lb0.x; Bs[nxt][bq + 1][brw] = lb0.y;
            Bs[nxt][bq + 2][brw] = lb0.z; Bs[nxt][bq + 3][brw] = lb0.w;
            Bs[nxt][bq + 0][brw + 64] = lb1.x; Bs[nxt][bq + 1][brw + 64] = lb1.y;
            Bs[nxt][bq + 2][brw + 64] = lb1.z; Bs[nxt][bq + 3][brw + 64] = lb1.w;
            __syncthreads();
            cur = nxt;
        }
    }

    // Epilogue: out[b*65536 + n*64 + k], fully coalesced float4.
#pragma unroll
    for (int i = 0; i < 8; ++i) {
        const int nIdx = n0 + ((i < 4) ? (ty + i) : (ty + 64 + i - 4));
#pragma unroll
        for (int jh = 0; jh < 2; ++jh) {
            const int rBase = r0 + jh * 64 + tx;  // (rBase & 63) == tx
            float4 o = make_float4(acc[i][jh * 4 + 0], acc[i][jh * 4 + 1],
                                   acc[i][jh * 4 + 2], acc[i][jh * 4 + 3]);
            *(float4*)(out + (size_t)(rBase >> 6) * (NN * NK) + (size_t)nIdx * NK + tx) = o;
        }
    }
}

// ---------------------------------------------------------------------------
extern "C" void kernel_launch(void* const* d_in, const int* in_sizes, int n_in,
                              void* d_out, int out_size) {
    (void)in_sizes; (void)n_in; (void)out_size;
    const float* x        = (const float*)d_in[0];  // [B, N*K]
    const float* A_logits = (const float*)d_in[1];  // [N, N]
    const float* W1       = (const float*)d_in[2];  // [N, 8]
    const float* WV       = (const float*)d_in[3];  // [8, K, K]
    const float* gamma2   = (const float*)d_in[4];  // [N]
    const float* beta2    = (const float*)d_in[5];  // [N]
    float* out = (float*)d_out;

    k_sink_row<<<NN, 256>>>(A_logits);
    k_sink_col<<<NN / 32, 256>>>();
    k_wsink<<<NN, 256>>>(W1, WV);
    k_xlocal<<<dim3(NN, NB / 64), 256>>>(x);
    k_lnt<<<dim3(NB, 2), 256>>>(gamma2, beta2);
    k_gemm<<<dim3(128, 8), 256>>>(out);
}

// round 6
// speedup vs baseline: 1.0009x; 1.0009x over previous
#include <cuda_runtime.h>
#include <math.h>
#include <stdint.h>

// Problem constants
#define NB 256        // batch B
#define NN 1024       // N
#define NK 64         // K
#define INV_TEMP 5.0f // 1/0.2
#define LN_EPS 1e-5f

// Scratch (static device globals; allocation inside kernel_launch is forbidden)
static __device__ float g_S[NN * NN];                    // sinkhorn(A_logits)   4 MB
static __device__ float g_W[NN * NK * NK];               // per-block sinkhorn  16 MB
static __device__ float g_XL[(size_t)NB * NN * NK];      // x_local [b][n][k]   64 MB
static __device__ float g_YT[(size_t)NB * NK * NN];      // normalized [b*K+k][n] 64 MB

// ---------------------------------------------------------------------------
// Kernel 1: row pass of log_sinkhorn on A_logits.
// la = logits/T ; la -= logsumexp(la, axis=-1) ; store to g_S.
// One block per row, 256 threads, 4 elements/thread.
// ---------------------------------------------------------------------------
__global__ void k_sink_row(const float* __restrict__ logits) {
    const int row = blockIdx.x;
    const int t = threadIdx.x;
    const float* rp = logits + (size_t)row * NN;
    float v[4];
    float m = -1e30f;
#pragma unroll
    for (int q = 0; q < 4; ++q) {
        v[q] = rp[t + 256 * q] * INV_TEMP;
        m = fmaxf(m, v[q]);
    }
    __shared__ float red[256];
    red[t] = m;
    __syncthreads();
    for (int s = 128; s > 0; s >>= 1) {
        if (t < s) red[t] = fmaxf(red[t], red[t + s]);
        __syncthreads();
    }
    m = red[0];
    __syncthreads();
    float acc = 0.f;
#pragma unroll
    for (int q = 0; q < 4; ++q) acc += expf(v[q] - m);
    red[t] = acc;
    __syncthreads();
    for (int s = 128; s > 0; s >>= 1) {
        if (t < s) red[t] += red[t + s];
        __syncthreads();
    }
    const float lse = logf(red[0]) + m;
    float* op = g_S + (size_t)row * NN;
#pragma unroll
    for (int q = 0; q < 4; ++q) op[t + 256 * q] = v[q] - lse;
}

// ---------------------------------------------------------------------------
// Kernel 2: column pass + exp. Each block owns 32 columns; 8-way row
// parallelism per column with online logsumexp, then in-place exp.
// ---------------------------------------------------------------------------
__global__ void k_sink_col() {
    const int c0 = blockIdx.x * 32;
    const int t = threadIdx.x;
    const int c = t & 31;
    const int ry = t >> 5;  // 0..7
    float m = -1e30f, s = 0.f;
    for (int i = ry; i < NN; i += 8) {
        float v = g_S[(size_t)i * NN + c0 + c];
        float mn = fmaxf(m, v);
        s = s * expf(m - mn) + expf(v - mn);
        m = mn;
    }
    __shared__ float sm[8][32];
    __shared__ float ss[8][32];
    __shared__ float cl[32];
    sm[ry][c] = m;
    ss[ry][c] = s;
    __syncthreads();
    if (t < 32) {
        float M = -1e30f;
#pragma unroll
        for (int q = 0; q < 8; ++q) M = fmaxf(M, sm[q][t]);
        float S = 0.f;
#pragma unroll
        for (int q = 0; q < 8; ++q) S += ss[q][t] * expf(sm[q][t] - M);
        cl[t] = logf(S) + M;
    }
    __syncthreads();
    const float myl = cl[c];
    for (int i = ry; i < NN; i += 8) {
        size_t idx = (size_t)i * NN + c0 + c;
        g_S[idx] = expf(g_S[idx] - myl);
    }
}

// ---------------------------------------------------------------------------
// Kernel 3: W[t] = log_sinkhorn( (W1[t,:] . W_V) / T ) for each t.
// One block per t; 64x64 logits live in smem; row LSE then column LSE.
// ---------------------------------------------------------------------------
__global__ void k_wsink(const float* __restrict__ W1, const float* __restrict__ WV) {
    const int n = blockIdx.x;
    const int t = threadIdx.x;
    __shared__ float L[64][65];
    __shared__ float w1[8];
    __shared__ float rl[64];
    __shared__ float cl[64];
    if (t < 8) w1[t] = W1[n * 8 + t];
    __syncthreads();
#pragma unroll
    for (int q = 0; q < 16; ++q) {
        int idx = t + 256 * q;
        float acc = 0.f;
#pragma unroll
        for (int k = 0; k < 8; ++k) acc += w1[k] * WV[k * 4096 + idx];
        L[idx >> 6][idx & 63] = acc * INV_TEMP;
    }
    __syncthreads();
    if (t < 64) {  // row logsumexp (over last axis e)
        float m = -1e30f;
        for (int e = 0; e < 64; ++e) m = fmaxf(m, L[t][e]);
        float s = 0.f;
        for (int e = 0; e < 64; ++e) s += expf(L[t][e] - m);
        rl[t] = logf(s) + m;
    }
    __syncthreads();
#pragma unroll
    for (int q = 0; q < 16; ++q) {
        int idx = t + 256 * q;
        L[idx >> 6][idx & 63] -= rl[idx >> 6];
    }
    __syncthreads();
    if (t < 64) {  // column logsumexp (over axis d)
        float m = -1e30f;
        for (int d = 0; d < 64; ++d) m = fmaxf(m, L[d][t]);
        float s = 0.f;
        for (int d = 0; d < 64; ++d) s += expf(L[d][t] - m);
        cl[t] = logf(s) + m;
    }
    __syncthreads();
    float* wp = g_W + (size_t)n * 4096;
#pragma unroll
    for (int q = 0; q < 16; ++q) {
        int idx = t + 256 * q;
        wp[idx] = expf(L[idx >> 6][idx & 63] - cl[idx & 63]);
    }
}

// ---------------------------------------------------------------------------
// Kernel 4: x_local[b,n,o] = sum_i x[b,n,i] * W[n,i,o].
// Block: one n, 64 batch rows. 16x16 threads, 4x4 microtile. Output stored
// [b][n][k] (coalesced float4 writes).
// ---------------------------------------------------------------------------
__global__ void k_xlocal(const float* __restrict__ x) {
    const int n = blockIdx.x;
    const int b0 = blockIdx.y * 64;
    const int t = threadIdx.x;
    __shared__ float Xs[64][68];
    __shared__ float Ws[64][68];
#pragma unroll
    for (int q = 0; q < 4; ++q) {
        int f4 = t + 256 * q;      // 0..1023
        int row = f4 >> 4;
        int ch = (f4 & 15) << 2;
        float4 vx = *(const float4*)(x + (size_t)(b0 + row) * (NN * NK) + n * NK + ch);
        *(float4*)&Xs[row][ch] = vx;
        float4 vw = *(const float4*)(g_W + (size_t)n * (NK * NK) + row * NK + ch);
        *(float4*)&Ws[row][ch] = vw;
    }
    __syncthreads();
    const int tx = (t & 15) << 2;  // output col o
    const int ty = (t >> 4) << 2;  // output row bb
    float acc[4][4] = {};
#pragma unroll 8
    for (int i = 0; i < 64; ++i) {
        float a[4];
#pragma unroll
        for (int j = 0; j < 4; ++j) a[j] = Xs[ty + j][i];
        float4 bv = *(float4*)&Ws[i][tx];
        float bb[4] = {bv.x, bv.y, bv.z, bv.w};
#pragma unroll
        for (int j = 0; j < 4; ++j)
#pragma unroll
            for (int jj = 0; jj < 4; ++jj)
                acc[j][jj] = fmaf(a[j], bb[jj], acc[j][jj]);
    }
#pragma unroll
    for (int j = 0; j < 4; ++j) {
        float4 o = make_float4(acc[j][0], acc[j][1], acc[j][2], acc[j][3]);
        *(float4*)(g_XL + ((size_t)(b0 + ty + j) * NN + n) * NK + tx) = o;
    }
}

// ---------------------------------------------------------------------------
// Kernel 5: layernorm over n (per (b,k)) + transpose to g_YT[(b*K+k)][n].
// Block: one b, 32 k-columns. Pass 1: coalesced stats. Pass 2: 32x32 smem
// tile transpose so writes are n-contiguous.
// ---------------------------------------------------------------------------
__global__ void k_lnt(const float* __restrict__ gamma2, const float* __restrict__ beta2) {
    const int b = blockIdx.x;
    const int k0 = blockIdx.y * 32;
    const int t = threadIdx.x;
    const int kc = t & 31;
    const int nr = t >> 5;  // 0..7
    const float* base = g_XL + (size_t)b * NN * NK;
    float s = 0.f, s2 = 0.f;
    for (int n = nr; n < NN; n += 8) {
        float v = base[(size_t)n * NK + k0 + kc];
        s += v;
        s2 += v * v;
    }
    __shared__ float ps[8][32];
    __shared__ float ps2[8][32];
    ps[nr][kc] = s;
    ps2[nr][kc] = s2;
    __syncthreads();
    __shared__ float mu[32];
    __shared__ float rstd_s[32];
    if (t < 32) {
        float S = 0.f, S2 = 0.f;
#pragma unroll
        for (int q = 0; q < 8; ++q) { S += ps[q][t]; S2 += ps2[q][t]; }
        float m = S * (1.0f / NN);
        float var = S2 * (1.0f / NN) - m * m;
        mu[t] = m;
        rstd_s[t] = rsqrtf(var + LN_EPS);
    }
    __syncthreads();
    __shared__ float T[32][33];
    for (int nt = 0; nt < NN; nt += 32) {
#pragma unroll
        for (int p = 0; p < 4; ++p) {
            int nl = nr + 8 * p;
            T[nl][kc] = base[(size_t)(nt + nl) * NK + k0 + kc];
        }
        __syncthreads();
#pragma unroll
        for (int p = 0; p < 4; ++p) {
            int kl = nr + 8 * p;
            int n = nt + kc;
            float v = (T[kc][kl] - mu[kl]) * rstd_s[kl];
            v = v * gamma2[n] + beta2[n];
            g_YT[(size_t)(b * NK + k0 + kl) * NN + n] = v;
        }
        __syncthreads();
    }
}

// ---------------------------------------------------------------------------
// Kernel 6: big GEMM, transposed formulation.
//   C[nIdx][r] = sum_m g_S[m][nIdx] * g_YT[r][m],  r = b*64 + k
//   out[b*65536 + nIdx*64 + k] = C[nIdx][r]
// 128x128x16 tile, 256 threads, 8x8 microtile, double-buffered smem.
// All LDG/STG are coalesced float4.
// ---------------------------------------------------------------------------
__global__ void __launch_bounds__(256) k_gemm(float* __restrict__ out) {
    const int br = blockIdx.x;  // r tile (0..127)
    const int bn = blockIdx.y;  // n tile (0..7)
    const int t = threadIdx.x;
    __shared__ float As[2][16][128];
    __shared__ float Bs[2][16][132];
    const int n0 = bn * 128;
    const int r0 = br * 128;

    const int am = t >> 5;            // As rows am, am+8
    const int an = (t & 31) << 2;     // As col chunk
    const int brw = t >> 2;           // Bs source rows brw, brw+64
    const int bq = (t & 3) << 2;      // m chunk within a Y row

    float4 la0, la1, lb0, lb1;
    la0 = *(const float4*)(g_S + (size_t)am * NN + n0 + an);
    la1 = *(const float4*)(g_S + (size_t)(am + 8) * NN + n0 + an);
    lb0 = *(const float4*)(g_YT + (size_t)(r0 + brw) * NN + bq);
    lb1 = *(const float4*)(g_YT + (size_t)(r0 + brw + 64) * NN + bq);
    *(float4*)&As[0][am][an] = la0;
    *(float4*)&As[0][am + 8][an] = la1;
    Bs[0][bq + 0][brw] = lb0.x; Bs[0][bq + 1][brw] = lb0.y;
    Bs[0][bq + 2][brw] = lb0.z; Bs[0][bq + 3][brw] = lb0.w;
    Bs[0][bq + 0][brw + 64] = lb1.x; Bs[0][bq + 1][brw + 64] = lb1.y;
    Bs[0][bq + 2][brw + 64] = lb1.z; Bs[0][bq + 3][brw + 64] = lb1.w;
    __syncthreads();

    const int tx = (t & 15) << 2;  // r micro base
    const int ty = (t >> 4) << 2;  // n micro base
    float acc[8][8] = {};
    int cur = 0;
#pragma unroll 1
    for (int it = 0; it < 64; ++it) {
        if (it < 63) {
            const int m0 = (it + 1) * 16;
            la0 = *(const float4*)(g_S + (size_t)(m0 + am) * NN + n0 + an);
            la1 = *(const float4*)(g_S + (size_t)(m0 + am + 8) * NN + n0 + an);
            lb0 = *(const float4*)(g_YT + (size_t)(r0 + brw) * NN + m0 + bq);
            lb1 = *(const float4*)(g_YT + (size_t)(r0 + brw + 64) * NN + m0 + bq);
        }
#pragma unroll
        for (int kk = 0; kk < 16; ++kk) {
            float ar[8], bv[8];
            *(float4*)(ar)     = *(float4*)&As[cur][kk][ty];
            *(float4*)(ar + 4) = *(float4*)&As[cur][kk][ty + 64];
            *(float4*)(bv)     = *(float4*)&Bs[cur][kk][tx];
            *(float4*)(bv + 4) = *(float4*)&Bs[cur][kk][tx + 64];
#pragma unroll
            for (int i = 0; i < 8; ++i)
#pragma unroll
                for (int j = 0; j < 8; ++j)
                    acc[i][j] = fmaf(ar[i], bv[j], acc[i][j]);
        }
        if (it < 63) {
            const int nxt = cur ^ 1;
            *(float4*)&As[nxt][am][an] = la0;
            *(float4*)&As[nxt][am + 8][an] = la1;
            Bs[nxt][bq + 0][brw] = lb0.x; Bs[nxt][bq + 1][brw] = lb0.y;
            Bs[nxt][bq + 2][brw] = lb0.z; Bs[nxt][bq + 3][brw] = lb0.w;
            Bs[nxt][bq + 0][brw + 64] = lb1.x; Bs[nxt][bq + 1][brw + 64] = lb1.y;
            Bs[nxt][bq + 2][brw + 64] = lb1.z; Bs[nxt][bq + 3][brw + 64] = lb1.w;
            __syncthreads();
            cur = nxt;
        }
    }

    // Epilogue: out[b*65536 + n*64 + k], fully coalesced float4.
#pragma unroll
    for (int i = 0; i < 8; ++i) {
        const int nIdx = n0 + ((i < 4) ? (ty + i) : (ty + 64 + i - 4));
#pragma unroll
        for (int jh = 0; jh < 2; ++jh) {
            const int rBase = r0 + jh * 64 + tx;  // (rBase & 63) == tx
            float4 o = make_float4(acc[i][jh * 4 + 0], acc[i][jh * 4 + 1],
                                   acc[i][jh * 4 + 2], acc[i][jh * 4 + 3]);
            *(float4*)(out + (size_t)(rBase >> 6) * (NN * NK) + (size_t)nIdx * NK + tx) = o;
        }
    }
}

// ---------------------------------------------------------------------------
extern "C" void kernel_launch(void* const* d_in, const int* in_sizes, int n_in,
                              void* d_out, int out_size) {
    (void)in_sizes; (void)n_in; (void)out_size;
    const float* x        = (const float*)d_in[0];  // [B, N*K]
    const float* A_logits = (const float*)d_in[1];  // [N, N]
    const float* W1       = (const float*)d_in[2];  // [N, 8]
    const float* WV       = (const float*)d_in[3];  // [8, K, K]
    const float* gamma2   = (const float*)d_in[4];  // [N]
    const float* beta2    = (const float*)d_in[5];  // [N]
    float* out = (float*)d_out;

    k_sink_row<<<NN, 256>>>(A_logits);
    k_sink_col<<<NN / 32, 256>>>();
    k_wsink<<<NN, 256>>>(W1, WV);
    k_xlocal<<<dim3(NN, NB / 64), 256>>>(x);
    k_lnt<<<dim3(NB, 2), 256>>>(gamma2, beta2);
    k_gemm<<<dim3(128, 8), 256>>>(out);
}